// round 8
// baseline (speedup 1.0000x reference)
#include <cuda_runtime.h>
#include <cstdint>

// Problem constants (fixed by reference: B=32, S=2048, D=512)
#define PB 32
#define PS 2048
#define D8 64               // float8 (32B) chunks per (b,s) position

// Scratch: rank per (b,s). rank >= 0 iff mask set; -1 otherwise.
__device__ int g_rank[PB * PS];

// ---------------------------------------------------------------------------
// 256-bit load/store helpers (Blackwell sm_100+: ld/st.global.v8.f32)
// ---------------------------------------------------------------------------
__device__ __forceinline__ void ldg_cs_v8(const float* __restrict__ p, float v[8])
{
    asm volatile("ld.global.cs.v8.f32 {%0,%1,%2,%3,%4,%5,%6,%7}, [%8];"
                 : "=f"(v[0]), "=f"(v[1]), "=f"(v[2]), "=f"(v[3]),
                   "=f"(v[4]), "=f"(v[5]), "=f"(v[6]), "=f"(v[7])
                 : "l"(p));
}

__device__ __forceinline__ void ldg_nc_v8(const float* __restrict__ p, float v[8])
{
    asm volatile("ld.global.nc.v8.f32 {%0,%1,%2,%3,%4,%5,%6,%7}, [%8];"
                 : "=f"(v[0]), "=f"(v[1]), "=f"(v[2]), "=f"(v[3]),
                   "=f"(v[4]), "=f"(v[5]), "=f"(v[6]), "=f"(v[7])
                 : "l"(p));
}

__device__ __forceinline__ void stg_cs_v8(float* __restrict__ p, const float v[8])
{
    asm volatile("st.global.cs.v8.f32 [%0], {%1,%2,%3,%4,%5,%6,%7,%8};"
                 :: "l"(p),
                    "f"(v[0]), "f"(v[1]), "f"(v[2]), "f"(v[3]),
                    "f"(v[4]), "f"(v[5]), "f"(v[6]), "f"(v[7])
                 : "memory");
}

// ---------------------------------------------------------------------------
// Kernel 1: per-row rank via ballot/popc scan (measured R7 version).
// One block (1024 threads = 32 warps) per row; two passes of 1024 positions.
// ---------------------------------------------------------------------------
__global__ void __launch_bounds__(1024, 1)
rank_scan_kernel(const int* __restrict__ masks)
{
    const int b = blockIdx.x;
    const int* m = masks + (size_t)b * PS;
    int*       r = g_rank + (size_t)b * PS;

    const int t    = threadIdx.x;
    const int lane = t & 31;
    const int w    = t >> 5;                 // 0..31

    __shared__ int warp_cnt[64];
    __shared__ int warp_off[64];

    const int p0 = t;
    const int p1 = t + 1024;
    const int m0 = (m[p0] != 0);
    const int m1 = (m[p1] != 0);

    const unsigned bal0 = __ballot_sync(0xFFFFFFFFu, m0);
    const unsigned bal1 = __ballot_sync(0xFFFFFFFFu, m1);

    if (lane == 0) {
        warp_cnt[w]      = __popc(bal0);
        warp_cnt[w + 32] = __popc(bal1);
    }
    __syncthreads();

    if (w == 0) {
        const int c0 = warp_cnt[lane];
        const int c1 = warp_cnt[lane + 32];

        int incl = c0;
        #pragma unroll
        for (int off = 1; off < 32; off <<= 1) {
            int v = __shfl_up_sync(0xFFFFFFFFu, incl, off);
            if (lane >= off) incl += v;
        }
        const int total0 = __shfl_sync(0xFFFFFFFFu, incl, 31);
        warp_off[lane] = incl - c0;

        int incl1 = c1;
        #pragma unroll
        for (int off = 1; off < 32; off <<= 1) {
            int v = __shfl_up_sync(0xFFFFFFFFu, incl1, off);
            if (lane >= off) incl1 += v;
        }
        warp_off[lane + 32] = total0 + incl1 - c1;
    }
    __syncthreads();

    const unsigned lt = (1u << lane) - 1u;
    const int rank0 = warp_off[w]      + __popc(bal0 & lt);
    const int rank1 = warp_off[w + 32] + __popc(bal1 & lt);

    r[p0] = m0 ? rank0 : -1;
    r[p1] = m1 ? rank1 : -1;
}

// ---------------------------------------------------------------------------
// Kernel 2: out = seqs + (rank >= 0 ? pe[rank] : 0), 256-bit vectorized.
// 256 threads/block, 2 float8 (32B) per thread, front-batched loads.
// idx is in float8 units: row = idx >> 6, col8 = idx & 63.
// ---------------------------------------------------------------------------
__global__ void __launch_bounds__(256, 8)
pe_add_kernel(const float* __restrict__ seqs,
              const float* __restrict__ pe,
              float*       __restrict__ out)
{
    const unsigned t    = threadIdx.x;
    const unsigned idx0 = blockIdx.x * 512u + t;       // float8 index 0
    const unsigned idx1 = idx0 + 256u;                 // float8 index 1

    const unsigned row0 = idx0 >> 6;
    const unsigned row1 = idx1 >> 6;
    const unsigned col0 = idx0 & 63u;
    const unsigned col1 = idx1 & 63u;

    // Front-batch all independent loads
    const int r0 = __ldg(&g_rank[row0]);
    const int r1 = __ldg(&g_rank[row1]);

    float v0[8], v1[8];
    ldg_cs_v8(seqs + (size_t)idx0 * 8u, v0);
    ldg_cs_v8(seqs + (size_t)idx1 * 8u, v1);

    if (r0 >= 0) {
        float p[8];
        ldg_nc_v8(pe + ((size_t)(unsigned)r0 * D8 + col0) * 8u, p);
        #pragma unroll
        for (int i = 0; i < 8; i++) v0[i] += p[i];
    }
    if (r1 >= 0) {
        float p[8];
        ldg_nc_v8(pe + ((size_t)(unsigned)r1 * D8 + col1) * 8u, p);
        #pragma unroll
        for (int i = 0; i < 8; i++) v1[i] += p[i];
    }

    stg_cs_v8(out + (size_t)idx0 * 8u, v0);
    stg_cs_v8(out + (size_t)idx1 * 8u, v1);
}

// ---------------------------------------------------------------------------
// Launch.
// Inputs (metadata order): seqs [B,S,D] f32, masks [B,S] int32, pe [2048,D] f32
// Output: [B,S,D] f32
// ---------------------------------------------------------------------------
extern "C" void kernel_launch(void* const* d_in, const int* in_sizes, int n_in,
                              void* d_out, int out_size)
{
    const float* seqs  = (const float*)d_in[0];
    const int*   masks = (const int*)d_in[1];
    const float* pe    = (const float*)d_in[2];
    float*       out   = (float*)d_out;

    (void)in_sizes; (void)n_in; (void)out_size;

    rank_scan_kernel<<<PB, 1024>>>(masks);

    const unsigned total8 = (unsigned)PB * PS * D8;    // 4,194,304 float8
    pe_add_kernel<<<total8 / 512, 256>>>(seqs, pe, out);
}

// round 9
// speedup vs baseline: 1.0485x; 1.0485x over previous
#include <cuda_runtime.h>
#include <cstdint>

// Problem constants (fixed by reference: B=32, S=2048, D=512)
#define PB 32
#define PS 2048
#define D4 128              // float4 per (b,s) position

// Scratch: rank per (b,s). rank >= 0 iff mask set; -1 otherwise.
__device__ int g_rank[PB * PS];

// ---------------------------------------------------------------------------
// Kernel 1: blocks 0..31  -> per-row rank via ballot/popc scan (R7 version).
//           blocks 32..159 -> warm L2 with the 4 MiB pe table (idle SMs).
// ---------------------------------------------------------------------------
__global__ void __launch_bounds__(1024, 1)
rank_scan_kernel(const int* __restrict__ masks, const float4* __restrict__ pe)
{
    const int blk = blockIdx.x;
    const int t   = threadIdx.x;

    if (blk >= PB) {
        // ---- pe prefetch: 128 blocks x 1024 threads x 2 float4 = 262144 ----
        const unsigned pidx = (unsigned)(blk - PB) * 2048u + t;
        // Keep-alive L2-warming loads; results unused.
        float4 a = __ldg(pe + pidx);
        float4 c = __ldg(pe + pidx + 1024u);
        asm volatile("" :: "f"(a.x), "f"(c.x));
        return;
    }

    const int* m = masks + (size_t)blk * PS;
    int*       r = g_rank + (size_t)blk * PS;

    const int lane = t & 31;
    const int w    = t >> 5;                 // 0..31

    __shared__ int warp_cnt[64];
    __shared__ int warp_off[64];

    const int p0 = t;
    const int p1 = t + 1024;
    const int m0 = (m[p0] != 0);
    const int m1 = (m[p1] != 0);

    const unsigned bal0 = __ballot_sync(0xFFFFFFFFu, m0);
    const unsigned bal1 = __ballot_sync(0xFFFFFFFFu, m1);

    if (lane == 0) {
        warp_cnt[w]      = __popc(bal0);
        warp_cnt[w + 32] = __popc(bal1);
    }
    __syncthreads();

    if (w == 0) {
        const int c0 = warp_cnt[lane];
        const int c1 = warp_cnt[lane + 32];

        int incl = c0;
        #pragma unroll
        for (int off = 1; off < 32; off <<= 1) {
            int v = __shfl_up_sync(0xFFFFFFFFu, incl, off);
            if (lane >= off) incl += v;
        }
        const int total0 = __shfl_sync(0xFFFFFFFFu, incl, 31);
        warp_off[lane] = incl - c0;

        int incl1 = c1;
        #pragma unroll
        for (int off = 1; off < 32; off <<= 1) {
            int v = __shfl_up_sync(0xFFFFFFFFu, incl1, off);
            if (lane >= off) incl1 += v;
        }
        warp_off[lane + 32] = total0 + incl1 - c1;
    }
    __syncthreads();

    const unsigned lt = (1u << lane) - 1u;
    const int rank0 = warp_off[w]      + __popc(bal0 & lt);
    const int rank1 = warp_off[w + 32] + __popc(bal1 & lt);

    r[p0] = m0 ? rank0 : -1;
    r[p1] = m1 ? rank1 : -1;
}

// ---------------------------------------------------------------------------
// Kernel 2 (R7 measured-best config): out = seqs + (rank >= 0 ? pe[rank] : 0).
// 256 threads/block, 2 float4 per thread, front-batched loads; __ldcs/__stcs
// keep the 256 MiB streaming traffic from evicting the 4 MiB pe table in L2.
// ---------------------------------------------------------------------------
__global__ void __launch_bounds__(256, 8)
pe_add_kernel(const float4* __restrict__ seqs,
              const float4* __restrict__ pe,
              float4*       __restrict__ out)
{
    const unsigned t    = threadIdx.x;
    const unsigned idx0 = blockIdx.x * 512u + t;       // element 0
    const unsigned idx1 = idx0 + 256u;                 // element 1

    const unsigned row0 = idx0 >> 7;
    const unsigned row1 = idx1 >> 7;
    const unsigned col0 = idx0 & 127u;
    const unsigned col1 = idx1 & 127u;

    // Front-batch all independent loads
    const int r0 = __ldg(&g_rank[row0]);
    const int r1 = __ldg(&g_rank[row1]);
    float4 v0 = __ldcs(seqs + idx0);
    float4 v1 = __ldcs(seqs + idx1);

    if (r0 >= 0) {
        const float4 p = __ldg(pe + (unsigned)r0 * D4 + col0);
        v0.x += p.x; v0.y += p.y; v0.z += p.z; v0.w += p.w;
    }
    if (r1 >= 0) {
        const float4 p = __ldg(pe + (unsigned)r1 * D4 + col1);
        v1.x += p.x; v1.y += p.y; v1.z += p.z; v1.w += p.w;
    }

    __stcs(out + idx0, v0);
    __stcs(out + idx1, v1);
}

// ---------------------------------------------------------------------------
// Launch.
// Inputs (metadata order): seqs [B,S,D] f32, masks [B,S] int32, pe [2048,D] f32
// Output: [B,S,D] f32
// ---------------------------------------------------------------------------
extern "C" void kernel_launch(void* const* d_in, const int* in_sizes, int n_in,
                              void* d_out, int out_size)
{
    const float* seqs  = (const float*)d_in[0];
    const int*   masks = (const int*)d_in[1];
    const float* pe    = (const float*)d_in[2];
    float*       out   = (float*)d_out;

    (void)in_sizes; (void)n_in; (void)out_size;

    // 32 scan blocks + 128 pe-prefetch blocks in one launch
    rank_scan_kernel<<<PB + 128, 1024>>>(masks, (const float4*)pe);

    const unsigned total4 = (unsigned)PB * PS * D4;    // 8,388,608
    pe_add_kernel<<<total4 / 512, 256>>>(
        (const float4*)seqs, (const float4*)pe, (float4*)out);
}

// round 11
// speedup vs baseline: 1.0529x; 1.0042x over previous
#include <cuda_runtime.h>
#include <cstdint>

// Problem constants (fixed by reference: B=32, S=2048, D=512)
#define PB 32
#define PS 2048
#define D4 128              // float4 per (b,s) position

// Scratch: rank per (b,s). rank >= 0 iff mask set; -1 otherwise.
__device__ int g_rank[PB * PS];

// ---------------------------------------------------------------------------
// Kernel 1: per-row rank via ballot/popc scan (R7 measured version).
// One block (1024 threads = 32 warps) per row; two passes of 1024 positions.
// ---------------------------------------------------------------------------
__global__ void __launch_bounds__(1024, 1)
rank_scan_kernel(const int* __restrict__ masks)
{
    const int b = blockIdx.x;
    const int* m = masks + (size_t)b * PS;
    int*       r = g_rank + (size_t)b * PS;

    const int t    = threadIdx.x;
    const int lane = t & 31;
    const int w    = t >> 5;                 // 0..31

    __shared__ int warp_cnt[64];
    __shared__ int warp_off[64];

    const int p0 = t;
    const int p1 = t + 1024;
    const int m0 = (m[p0] != 0);
    const int m1 = (m[p1] != 0);

    const unsigned bal0 = __ballot_sync(0xFFFFFFFFu, m0);
    const unsigned bal1 = __ballot_sync(0xFFFFFFFFu, m1);

    if (lane == 0) {
        warp_cnt[w]      = __popc(bal0);
        warp_cnt[w + 32] = __popc(bal1);
    }
    __syncthreads();

    if (w == 0) {
        const int c0 = warp_cnt[lane];
        const int c1 = warp_cnt[lane + 32];

        int incl = c0;
        #pragma unroll
        for (int off = 1; off < 32; off <<= 1) {
            int v = __shfl_up_sync(0xFFFFFFFFu, incl, off);
            if (lane >= off) incl += v;
        }
        const int total0 = __shfl_sync(0xFFFFFFFFu, incl, 31);
        warp_off[lane] = incl - c0;

        int incl1 = c1;
        #pragma unroll
        for (int off = 1; off < 32; off <<= 1) {
            int v = __shfl_up_sync(0xFFFFFFFFu, incl1, off);
            if (lane >= off) incl1 += v;
        }
        warp_off[lane + 32] = total0 + incl1 - c1;
    }
    __syncthreads();

    const unsigned lt = (1u << lane) - 1u;
    const int rank0 = warp_off[w]      + __popc(bal0 & lt);
    const int rank1 = warp_off[w + 32] + __popc(bal1 & lt);

    r[p0] = m0 ? rank0 : -1;
    r[p1] = m1 ? rank1 : -1;
}

// ---------------------------------------------------------------------------
// Kernel 2 (R7 config + PDL): out = seqs + (rank >= 0 ? pe[rank] : 0).
// Launched with programmatic dependent launch: it starts while the scan is
// still running, front-issues its streaming loads, then
// cudaGridDependencySynchronize() guarantees g_rank visibility.
// ---------------------------------------------------------------------------
__global__ void __launch_bounds__(256, 8)
pe_add_kernel(const float4* __restrict__ seqs,
              const float4* __restrict__ pe,
              float4*       __restrict__ out)
{
    const unsigned t    = threadIdx.x;
    const unsigned idx0 = blockIdx.x * 512u + t;       // element 0
    const unsigned idx1 = idx0 + 256u;                 // element 1

    // Front-issue streaming loads — independent of the primary kernel.
    float4 v0 = __ldcs(seqs + idx0);
    float4 v1 = __ldcs(seqs + idx1);

    // Wait for the scan kernel's completion (architected, memory-ordered).
    cudaGridDependencySynchronize();

    // Plain coherent loads for ranks (written by the primary kernel).
    const int r0 = g_rank[idx0 >> 7];
    const int r1 = g_rank[idx1 >> 7];

    if (r0 >= 0) {
        const float4 p = __ldg(pe + (unsigned)r0 * D4 + (idx0 & 127u));
        v0.x += p.x; v0.y += p.y; v0.z += p.z; v0.w += p.w;
    }
    if (r1 >= 0) {
        const float4 p = __ldg(pe + (unsigned)r1 * D4 + (idx1 & 127u));
        v1.x += p.x; v1.y += p.y; v1.z += p.z; v1.w += p.w;
    }

    __stcs(out + idx0, v0);
    __stcs(out + idx1, v1);
}

// ---------------------------------------------------------------------------
// Launch: scan normally, pe_add via PDL so it overlaps the scan.
// Inputs (metadata order): seqs [B,S,D] f32, masks [B,S] int32, pe [2048,D] f32
// Output: [B,S,D] f32
// ---------------------------------------------------------------------------
extern "C" void kernel_launch(void* const* d_in, const int* in_sizes, int n_in,
                              void* d_out, int out_size)
{
    const float* seqs  = (const float*)d_in[0];
    const int*   masks = (const int*)d_in[1];
    const float* pe    = (const float*)d_in[2];
    float*       out   = (float*)d_out;

    (void)in_sizes; (void)n_in; (void)out_size;

    rank_scan_kernel<<<PB, 1024>>>(masks);

    const unsigned total4 = (unsigned)PB * PS * D4;    // 8,388,608

    cudaLaunchConfig_t cfg = {};
    cfg.gridDim  = dim3(total4 / 512, 1, 1);
    cfg.blockDim = dim3(256, 1, 1);
    cfg.dynamicSmemBytes = 0;
    cfg.stream = 0;

    cudaLaunchAttribute attr[1];
    attr[0].id = cudaLaunchAttributeProgrammaticStreamSerialization;
    attr[0].val.programmaticStreamSerializationAllowed = 1;
    cfg.attrs = attr;
    cfg.numAttrs = 1;

    cudaLaunchKernelEx(&cfg, pe_add_kernel,
                       (const float4*)seqs, (const float4*)pe, (float4*)out);
}